// round 5
// baseline (speedup 1.0000x reference)
#include <cuda_runtime.h>
#include <math.h>

#define SEQ 512
#define BB  64
#define EMB 512
#define HID 1024
#define NG  4096

typedef unsigned long long ull;

// ---------------- device scratch (no runtime allocation) ----------------
__device__ float d_gx[(size_t)SEQ * NG * BB];   // [s][n][b]  n = g*1024+j
__device__ float d_wxp[NG * EMB];               // packed Wx  [n][e]
__device__ float d_bxp[NG];
__device__ float d_whp[(size_t)NG * HID];       // packed Wh  [n][k]
__device__ float d_hbuf[2][BB * HID];           // ping-pong h   [b][k]
__device__ float d_cst[BB * HID];               // c state       [b][k]
__device__ int   d_bar;                         // grid barrier counter

// ---------------- helpers ----------------
__device__ __forceinline__ void fma2(ull& d, ull a, ull b) {
    asm("fma.rn.f32x2 %0, %1, %2, %0;" : "+l"(d) : "l"(a), "l"(b));
}
__device__ __forceinline__ float hsum2(ull v) {
    unsigned lo = (unsigned)(v & 0xffffffffULL);
    unsigned hi = (unsigned)(v >> 32);
    return __uint_as_float(lo) + __uint_as_float(hi);
}
__device__ __forceinline__ float sigf(float x) {
    return 1.0f / (1.0f + __expf(-x));
}
__device__ __forceinline__ void cp16(void* smem_dst, const void* gsrc) {
    unsigned d = (unsigned)__cvta_generic_to_shared(smem_dst);
    asm volatile("cp.async.cg.shared.global [%0], [%1], 16;" :: "r"(d), "l"(gsrc));
}
__device__ __forceinline__ void cp_commit() {
    asm volatile("cp.async.commit_group;");
}
template <int N>
__device__ __forceinline__ void cp_wait() {
    asm volatile("cp.async.wait_group %0;" :: "n"(N));
}

// =====================================================================
// prepack
// =====================================================================
__global__ void prepack_kernel(
    const float* __restrict__ W_ii, const float* __restrict__ b_ii, const float* __restrict__ W_hi,
    const float* __restrict__ W_if, const float* __restrict__ b_if, const float* __restrict__ W_hf,
    const float* __restrict__ W_ig, const float* __restrict__ b_ig, const float* __restrict__ W_hg,
    const float* __restrict__ W_io, const float* __restrict__ b_io, const float* __restrict__ W_ho)
{
    const int stride = gridDim.x * blockDim.x;
    const int tid = blockIdx.x * blockDim.x + threadIdx.x;

    if (tid == 0) d_bar = 0;

    for (int i = tid; i < NG * EMB; i += stride) {
        int n = i / EMB, k = i - n * EMB;
        int g = n >> 10, j = n & 1023;
        const float* w = (g == 0) ? W_ii : (g == 1) ? W_if : (g == 2) ? W_ig : W_io;
        d_wxp[i] = w[j * EMB + k];
    }
    for (int i = tid; i < NG * HID; i += stride) {
        int n = i >> 10, k = i & 1023;
        int g = n >> 10, j = n & 1023;
        const float* w = (g == 0) ? W_hi : (g == 1) ? W_hf : (g == 2) ? W_hg : W_ho;
        d_whp[i] = w[j * HID + k];
    }
    for (int i = tid; i < NG; i += stride) {
        int g = i >> 10, j = i & 1023;
        const float* b = (g == 0) ? b_ii : (g == 1) ? b_if : (g == 2) ? b_ig : b_io;
        d_bxp[i] = b[j];
    }
    for (int i = tid; i < BB * HID; i += stride) {
        d_hbuf[0][i] = 0.0f; d_hbuf[1][i] = 0.0f; d_cst[i] = 0.0f;
    }
}

// =====================================================================
// gx kernel: d_gx[s][n][b] = sum_e emb[x[b,s],e] * Wxp[n][e] + bxp[n]
// grid (64 ntiles, 512 s), 256 thr, 1 CTA/SM.
// 8 warps = ks(4) x rh(2). Lane: ngrp = lane>>3 (0..3), bgrp = lane&7.
// Thread tile 8r x 8b: rows r = rh*32 + ngrp + 4j (j<8),
//                      batch b = bgrp + 8p (p<8).
// K staged in 64-k chunks, double-buffered cp.async. Warp k-sub = ks*16.
// Pitches 68 / reduction 66 -> conflict-free phases.
// =====================================================================
#define GX_AS 68
#define GX_RS 66
#define GX_BUF (64 * GX_AS)                    // one tile buffer (words)
#define GX_SMEM ((4 * GX_BUF) * 4)             // A0,B0,A1,B1

__global__ void __launch_bounds__(256, 1) gx_kernel(const int* __restrict__ x,
                                                    const float* __restrict__ emb)
{
    extern __shared__ float sm[];
    float* shA0 = sm;                  // [64 b][68]
    float* shB0 = sm + GX_BUF;         // [64 n][68]
    float* shA1 = sm + 2 * GX_BUF;
    float* shB1 = sm + 3 * GX_BUF;
    float* red  = sm;                  // alias: [4 ks][64 r][66] = 16896 words

    const int t = threadIdx.x;
    const int s = blockIdx.y;
    const int n0 = blockIdx.x * 64;

    __shared__ int tok[64];
    if (t < 64) tok[t] = x[t * SEQ + s];

    const int w = t >> 5, lane = t & 31;
    const int ks = w & 3, rh = w >> 2;
    const int ngrp = lane >> 3, bgrp = lane & 7;

    ull acc[8][8];
#pragma unroll
    for (int j = 0; j < 8; j++)
#pragma unroll
        for (int p = 0; p < 8; p++) acc[j][p] = 0ULL;

    // staging map: f = t + i*256 ; row = f>>4, seg = f&15 (16B units)
    const int srow = t >> 4, sseg = (t & 15) * 4;

    __syncthreads();   // tok ready

    // prologue: chunk 0 -> buf0
#pragma unroll
    for (int i = 0; i < 4; i++) {
        int r = srow + i * 16;
        cp16(shA0 + r * GX_AS + sseg, emb + (size_t)tok[r] * EMB + 0 + sseg);
        cp16(shB0 + r * GX_AS + sseg, d_wxp + (size_t)(n0 + r) * EMB + 0 + sseg);
    }
    cp_commit();

    for (int ch = 0; ch < EMB; ch += 64) {
        const bool odd = (ch >> 6) & 1;
        float* curA = odd ? shA1 : shA0;
        float* curB = odd ? shB1 : shB0;
        float* nxtA = odd ? shA0 : shA1;
        float* nxtB = odd ? shB0 : shB1;
        if (ch + 64 < EMB) {
#pragma unroll
            for (int i = 0; i < 4; i++) {
                int r = srow + i * 16;
                cp16(nxtA + r * GX_AS + sseg, emb + (size_t)tok[r] * EMB + ch + 64 + sseg);
                cp16(nxtB + r * GX_AS + sseg, d_wxp + (size_t)(n0 + r) * EMB + ch + 64 + sseg);
            }
            cp_commit();
            cp_wait<1>();
        } else {
            cp_wait<0>();
        }
        __syncthreads();

#pragma unroll
        for (int it = 0; it < 4; it++) {
            const int kl = ks * 16 + it * 4;
            ulonglong2 hv[8];
#pragma unroll
            for (int p = 0; p < 8; p++)
                hv[p] = *(const ulonglong2*)(curA + (bgrp + 8 * p) * GX_AS + kl);
#pragma unroll
            for (int j = 0; j < 8; j++) {
                ulonglong2 wv = *(const ulonglong2*)(curB + (rh * 32 + ngrp + 4 * j) * GX_AS + kl);
#pragma unroll
                for (int p = 0; p < 8; p++) {
                    fma2(acc[j][p], wv.x, hv[p].x);
                    fma2(acc[j][p], wv.y, hv[p].y);
                }
            }
        }
        __syncthreads();   // done with cur before refill
    }

    // ---- k-split reduction through smem ----
#pragma unroll
    for (int j = 0; j < 8; j++)
#pragma unroll
        for (int p = 0; p < 8; p++) {
            int r = rh * 32 + ngrp + 4 * j;
            int b = bgrp + 8 * p;
            red[(ks * 64 + r) * GX_RS + b] = hsum2(acc[j][p]);
        }
    __syncthreads();
#pragma unroll
    for (int i = 0; i < 16; i++) {
        int cell = t + i * 256;
        int r = cell >> 6, b = cell & 63;
        float v = red[r * GX_RS + b] + red[(64 + r) * GX_RS + b]
                + red[(128 + r) * GX_RS + b] + red[(192 + r) * GX_RS + b]
                + d_bxp[n0 + r];
        d_gx[((size_t)s * NG + n0 + r) * BB + b] = v;
    }
}

// =====================================================================
// persistent recurrent kernel: 512 timesteps, 128 CTAs x 256 thr, 1/SM.
// W slice (32 rows x 1024) in SMEM once. 8 warps = pure k-split (ks=w),
// warp k-sub = ks*16 within each 128-k double-buffered chunk.
// Lane: ngrp = lane>>3, bgrp = lane&7; thread tile 8r x 8b:
//   rows r = ngrp + 4j (j<8), batch b = bgrp + 8p (p<8).
// =====================================================================
#define PS_WS 1028
#define PS_HS 132
#define PS_RS 66
#define PS_SMEM ((32 * PS_WS + 2 * 64 * PS_HS) * 4)

__global__ void __launch_bounds__(256, 1) persist_kernel()
{
    extern __shared__ float sm[];
    float* shW  = sm;                            // [32 r][1028]
    float* shH0 = sm + 32 * PS_WS;               // [64 b][132]
    float* shH1 = shH0 + 64 * PS_HS;             // [64 b][132]
    float* red  = shH0;                          // [8 ks][32 r][66] = 16896 words

    const int t = threadIdx.x;
    const int j0 = blockIdx.x * 8;
    const int w = t >> 5, lane = t & 31;
    const int ks = w;
    const int ngrp = lane >> 3, bgrp = lane & 7;

    // epilogue mapping: thread owns batch be, j-pair (2*jp, 2*jp+1)
    const int be = t & 63, jp = t >> 6;

    // ---- stage W slice once: 32 rows x 1024 k ----
#pragma unroll
    for (int i = 0; i < 32; i++) {
        int f = t + i * 256;
        int r = f >> 8, kq = (f & 255) << 2;
        int n = (r >> 3) * HID + j0 + (r & 7);   // gate = r>>3, jj = r&7
        float4 v = *(const float4*)(d_whp + (size_t)n * HID + kq);
        *(float4*)(shW + r * PS_WS + kq) = v;
    }

    float creg[2] = {0.0f, 0.0f};

    const int sb = t >> 5, skq = (t & 31) << 2;  // h staging: warp w stages rows w+8i

    for (int s = 0; s < SEQ; s++) {
        const float* __restrict__ hprev = d_hbuf[s & 1];
        float* __restrict__ hnext = d_hbuf[(s + 1) & 1];

        // ---- prefetch gx gates for this step (latency hidden by GEMM) ----
        float gpre[2][4];
#pragma unroll
        for (int i = 0; i < 2; i++)
#pragma unroll
            for (int gg = 0; gg < 4; gg++)
                gpre[i][gg] = __ldg(&d_gx[((size_t)s * NG + gg * 1024 + j0 + 2 * jp + i) * BB + be]);

        ull acc[8][8];
#pragma unroll
        for (int j = 0; j < 8; j++)
#pragma unroll
            for (int p = 0; p < 8; p++) acc[j][p] = 0ULL;

        __syncthreads();   // protect h buffers / red alias from previous step
#pragma unroll
        for (int i = 0; i < 8; i++) {
            int b = sb + i * 8;
            cp16(shH0 + b * PS_HS + skq, hprev + b * HID + 0 + skq);
        }
        cp_commit();

        for (int ch = 0; ch < HID; ch += 128) {
            float* cur = ((ch >> 7) & 1) ? shH1 : shH0;
            float* nxt = ((ch >> 7) & 1) ? shH0 : shH1;
            if (ch + 128 < HID) {
#pragma unroll
                for (int i = 0; i < 8; i++) {
                    int b = sb + i * 8;
                    cp16(nxt + b * PS_HS + skq, hprev + b * HID + ch + 128 + skq);
                }
                cp_commit();
                cp_wait<1>();
            } else {
                cp_wait<0>();
            }
            __syncthreads();

#pragma unroll
            for (int it = 0; it < 4; it++) {
                const int kh = ks * 16 + it * 4;      // within chunk
                ulonglong2 hv[8];
#pragma unroll
                for (int p = 0; p < 8; p++)
                    hv[p] = *(const ulonglong2*)(cur + (bgrp + 8 * p) * PS_HS + kh);
#pragma unroll
                for (int j = 0; j < 8; j++) {
                    ulonglong2 wv = *(const ulonglong2*)(shW + (ngrp + 4 * j) * PS_WS + ch + kh);
#pragma unroll
                    for (int p = 0; p < 8; p++) {
                        fma2(acc[j][p], wv.x, hv[p].x);
                        fma2(acc[j][p], wv.y, hv[p].y);
                    }
                }
            }
            __syncthreads();  // all warps done with 'cur' before refill
        }

        // ---- k-split reduction through smem (red aliases h bufs) ----
#pragma unroll
        for (int j = 0; j < 8; j++)
#pragma unroll
            for (int p = 0; p < 8; p++) {
                int r = ngrp + 4 * j;
                int b = bgrp + 8 * p;
                red[(ks * 32 + r) * PS_RS + b] = hsum2(acc[j][p]);
            }
        __syncthreads();

        // ---- pointwise LSTM cell update: thread = (batch be, j-pair jp) ----
        float2 hout;
#pragma unroll
        for (int i = 0; i < 2; i++) {
            int j = 2 * jp + i;
            float g[4];
#pragma unroll
            for (int gg = 0; gg < 4; gg++) {
                int r = gg * 8 + j;
                float v = 0.0f;
#pragma unroll
                for (int kk = 0; kk < 8; kk++)
                    v += red[(kk * 32 + r) * PS_RS + be];
                g[gg] = v + gpre[i][gg];
            }
            float it_ = sigf(g[0]);
            float ft  = sigf(g[1]);
            float gt  = tanhf(g[2]);
            float ot  = sigf(g[3]);
            float c = ft * creg[i] + it_ * gt;
            creg[i] = c;
            ((float*)&hout)[i] = ot * tanhf(c);
        }
        *(float2*)(hnext + be * HID + j0 + 2 * jp) = hout;

        // ---- grid-wide barrier ----
        __threadfence();
        __syncthreads();
        if (t == 0) {
            atomicAdd(&d_bar, 1);
            const int target = 128 * (s + 1);
            while (*(volatile int*)&d_bar < target) { }
        }
        __syncthreads();
    }

    // ---- publish final c ----
    *(float2*)(d_cst + be * HID + j0 + 2 * jp) = make_float2(creg[0], creg[1]);
}

// =====================================================================
// head: out = h @ V_w^T + V_b ; also emit h, c into d_out.
// =====================================================================
__global__ void head_kernel(const float* __restrict__ Vw, const float* __restrict__ Vb,
                            float* __restrict__ out)
{
    const float* hfin = d_hbuf[SEQ & 1];
    const int b = blockIdx.x, t = threadIdx.x;
    float s0 = 0.0f, s1 = 0.0f;
    for (int k = t; k < HID; k += 256) {
        float hv = hfin[b * HID + k];
        s0 += hv * Vw[k];
        s1 += hv * Vw[HID + k];
        out[128 + b * HID + k] = hv;
        out[128 + BB * HID + b * HID + k] = d_cst[b * HID + k];
    }
    __shared__ float r0[256], r1[256];
    r0[t] = s0; r1[t] = s1;
    __syncthreads();
    for (int off = 128; off > 0; off >>= 1) {
        if (t < off) { r0[t] += r0[t + off]; r1[t] += r1[t + off]; }
        __syncthreads();
    }
    if (t == 0) {
        out[b * 2 + 0] = r0[0] + Vb[0];
        out[b * 2 + 1] = r1[0] + Vb[1];
    }
}

// =====================================================================
extern "C" void kernel_launch(void* const* d_in, const int* in_sizes, int n_in,
                              void* d_out, int out_size)
{
    (void)in_sizes; (void)n_in; (void)out_size;
    const int*   x   = (const int*)d_in[0];
    const float* emb = (const float*)d_in[1];

    cudaFuncSetAttribute(gx_kernel,      cudaFuncAttributeMaxDynamicSharedMemorySize, GX_SMEM);
    cudaFuncSetAttribute(persist_kernel, cudaFuncAttributeMaxDynamicSharedMemorySize, PS_SMEM);

    prepack_kernel<<<1024, 256>>>(
        (const float*)d_in[2],  (const float*)d_in[3],  (const float*)d_in[4],
        (const float*)d_in[5],  (const float*)d_in[6],  (const float*)d_in[7],
        (const float*)d_in[8],  (const float*)d_in[9],  (const float*)d_in[10],
        (const float*)d_in[11], (const float*)d_in[12], (const float*)d_in[13]);

    gx_kernel<<<dim3(64, 512), 256, GX_SMEM>>>(x, emb);

    persist_kernel<<<128, 256, PS_SMEM>>>();

    head_kernel<<<BB, 256>>>((const float*)d_in[14], (const float*)d_in[15], (float*)d_out);
}

// round 6
// speedup vs baseline: 1.0546x; 1.0546x over previous
#include <cuda_runtime.h>
#include <math.h>

#define SEQ 512
#define BB  64
#define EMB 512
#define HID 1024
#define NG  4096

typedef unsigned long long ull;

// ---------------- device scratch (no runtime allocation) ----------------
__device__ float d_gx[(size_t)SEQ * NG * BB];   // [s][n][b]  n = g*1024+j
__device__ float d_wxp[NG * EMB];               // packed Wx  [n][e]
__device__ float d_bxp[NG];
__device__ float d_whp[(size_t)NG * HID];       // packed Wh  [n][k]
__device__ float d_hbuf[2][BB * HID];           // ping-pong h   [b][k]
__device__ float d_cst[BB * HID];               // c state       [b][k]
__device__ int   d_bar;                         // grid barrier counter

// ---------------- helpers ----------------
__device__ __forceinline__ void fma2(ull& d, ull a, ull b) {
    asm("fma.rn.f32x2 %0, %1, %2, %0;" : "+l"(d) : "l"(a), "l"(b));
}
__device__ __forceinline__ float hsum2(ull v) {
    unsigned lo = (unsigned)(v & 0xffffffffULL);
    unsigned hi = (unsigned)(v >> 32);
    return __uint_as_float(lo) + __uint_as_float(hi);
}
__device__ __forceinline__ float sigf(float x) {
    return 1.0f / (1.0f + __expf(-x));
}
__device__ __forceinline__ void cp16(void* smem_dst, const void* gsrc) {
    unsigned d = (unsigned)__cvta_generic_to_shared(smem_dst);
    asm volatile("cp.async.cg.shared.global [%0], [%1], 16;" :: "r"(d), "l"(gsrc));
}
__device__ __forceinline__ void cp_commit() {
    asm volatile("cp.async.commit_group;");
}
template <int N>
__device__ __forceinline__ void cp_wait() {
    asm volatile("cp.async.wait_group %0;" :: "n"(N));
}

// =====================================================================
// prepack
// =====================================================================
__global__ void prepack_kernel(
    const float* __restrict__ W_ii, const float* __restrict__ b_ii, const float* __restrict__ W_hi,
    const float* __restrict__ W_if, const float* __restrict__ b_if, const float* __restrict__ W_hf,
    const float* __restrict__ W_ig, const float* __restrict__ b_ig, const float* __restrict__ W_hg,
    const float* __restrict__ W_io, const float* __restrict__ b_io, const float* __restrict__ W_ho)
{
    const int stride = gridDim.x * blockDim.x;
    const int tid = blockIdx.x * blockDim.x + threadIdx.x;

    if (tid == 0) d_bar = 0;

    for (int i = tid; i < NG * EMB; i += stride) {
        int n = i / EMB, k = i - n * EMB;
        int g = n >> 10, j = n & 1023;
        const float* w = (g == 0) ? W_ii : (g == 1) ? W_if : (g == 2) ? W_ig : W_io;
        d_wxp[i] = w[j * EMB + k];
    }
    for (int i = tid; i < NG * HID; i += stride) {
        int n = i >> 10, k = i & 1023;
        int g = n >> 10, j = n & 1023;
        const float* w = (g == 0) ? W_hi : (g == 1) ? W_hf : (g == 2) ? W_hg : W_ho;
        d_whp[i] = w[j * HID + k];
    }
    for (int i = tid; i < NG; i += stride) {
        int g = i >> 10, j = i & 1023;
        const float* b = (g == 0) ? b_ii : (g == 1) ? b_if : (g == 2) ? b_ig : b_io;
        d_bxp[i] = b[j];
    }
    for (int i = tid; i < BB * HID; i += stride) {
        d_hbuf[0][i] = 0.0f; d_hbuf[1][i] = 0.0f; d_cst[i] = 0.0f;
    }
}

// =====================================================================
// gx kernel: d_gx[s][n][b] = sum_e emb[x[b,s],e] * Wxp[n][e] + bxp[n]
// grid (64 ntiles, 512 s), 256 thr, 2 CTAs/SM.
// 8 warps = ks(2) x rq(4). Warp owns rows rq*16..rq*16+15, k-sub ks*32
// within each 64-k double-buffered chunk. Lanes split batch only:
// lane owns b = lane and lane+32. W read as warp-uniform LDS.128
// broadcast (1 wavefront); h as two distinct LDS.128 per 4-k.
// acc[16][2] f32x2 (k-pair packed).
// =====================================================================
#define GX_AS 68
#define GX_RS 66
#define GX_BUF (64 * GX_AS)                    // one tile buffer (words)
#define GX_SMEM ((4 * GX_BUF) * 4)             // A0,B0,A1,B1

__global__ void __launch_bounds__(256, 2) gx_kernel(const int* __restrict__ x,
                                                    const float* __restrict__ emb)
{
    extern __shared__ float sm[];
    float* shA0 = sm;                  // [64 b][68]
    float* shB0 = sm + GX_BUF;         // [64 n][68]
    float* shA1 = sm + 2 * GX_BUF;
    float* shB1 = sm + 3 * GX_BUF;
    float* red  = sm;                  // alias: [2 ks][64 r][66] = 8448 words

    const int t = threadIdx.x;
    const int s = blockIdx.y;
    const int n0 = blockIdx.x * 64;

    __shared__ int tok[64];
    if (t < 64) tok[t] = x[t * SEQ + s];

    const int w = t >> 5, lane = t & 31;
    const int ks = w & 1, rq = w >> 1;

    ull acc[16][2];
#pragma unroll
    for (int r = 0; r < 16; r++) { acc[r][0] = 0ULL; acc[r][1] = 0ULL; }

    // staging map: f = t + i*256 ; row = f>>4, seg = (f&15)*4 words
    const int srow = t >> 4, sseg = (t & 15) * 4;

    __syncthreads();   // tok ready

    // prologue: chunk 0 -> buf0
#pragma unroll
    for (int i = 0; i < 4; i++) {
        int r = srow + i * 16;
        cp16(shA0 + r * GX_AS + sseg, emb + (size_t)tok[r] * EMB + 0 + sseg);
        cp16(shB0 + r * GX_AS + sseg, d_wxp + (size_t)(n0 + r) * EMB + 0 + sseg);
    }
    cp_commit();

    for (int ch = 0; ch < EMB; ch += 64) {
        const bool odd = (ch >> 6) & 1;
        float* curA = odd ? shA1 : shA0;
        float* curB = odd ? shB1 : shB0;
        float* nxtA = odd ? shA0 : shA1;
        float* nxtB = odd ? shB0 : shB1;
        if (ch + 64 < EMB) {
#pragma unroll
            for (int i = 0; i < 4; i++) {
                int r = srow + i * 16;
                cp16(nxtA + r * GX_AS + sseg, emb + (size_t)tok[r] * EMB + ch + 64 + sseg);
                cp16(nxtB + r * GX_AS + sseg, d_wxp + (size_t)(n0 + r) * EMB + ch + 64 + sseg);
            }
            cp_commit();
            cp_wait<1>();
        } else {
            cp_wait<0>();
        }
        __syncthreads();

#pragma unroll
        for (int it = 0; it < 8; it++) {
            const int kl = ks * 32 + it * 4;
            ulonglong2 hv0 = *(const ulonglong2*)(curA + lane * GX_AS + kl);
            ulonglong2 hv1 = *(const ulonglong2*)(curA + (lane + 32) * GX_AS + kl);
#pragma unroll
            for (int r = 0; r < 16; r++) {
                ulonglong2 wv = *(const ulonglong2*)(curB + (rq * 16 + r) * GX_AS + kl);
                fma2(acc[r][0], wv.x, hv0.x);
                fma2(acc[r][0], wv.y, hv0.y);
                fma2(acc[r][1], wv.x, hv1.x);
                fma2(acc[r][1], wv.y, hv1.y);
            }
        }
        __syncthreads();   // done with cur before refill
    }

    // ---- k-split reduction through smem ----
#pragma unroll
    for (int r = 0; r < 16; r++) {
        int rr = rq * 16 + r;
        red[(ks * 64 + rr) * GX_RS + lane]      = hsum2(acc[r][0]);
        red[(ks * 64 + rr) * GX_RS + lane + 32] = hsum2(acc[r][1]);
    }
    __syncthreads();
#pragma unroll
    for (int i = 0; i < 16; i++) {
        int cell = t + i * 256;
        int r = cell >> 6, b = cell & 63;
        float v = red[r * GX_RS + b] + red[(64 + r) * GX_RS + b] + d_bxp[n0 + r];
        d_gx[((size_t)s * NG + n0 + r) * BB + b] = v;
    }
}

// =====================================================================
// persistent recurrent kernel: 512 timesteps, 128 CTAs x 256 thr, 1/SM.
// W slice (32 rows x 1024) in SMEM once. 8 warps = ks(4) x rh(2).
// Warp owns rows rh*16..rh*16+15, k-sub ks*32 within each 128-k chunk.
// Lanes split batch only (b = lane, lane+32); W via LDS.128 broadcast.
// acc[16][2] f32x2 k-pair packed. c in registers. Grid barrier per step.
// =====================================================================
#define PS_WS 1028
#define PS_HS 132
#define PS_RS 66
#define PS_SMEM ((32 * PS_WS + 2 * 64 * PS_HS) * 4)

__global__ void __launch_bounds__(256, 1) persist_kernel()
{
    extern __shared__ float sm[];
    float* shW  = sm;                            // [32 r][1028]
    float* shH0 = sm + 32 * PS_WS;               // [64 b][132]
    float* shH1 = shH0 + 64 * PS_HS;             // [64 b][132]
    float* red  = shH0;                          // [4 ks][32 r][66] = 8448 words

    const int t = threadIdx.x;
    const int j0 = blockIdx.x * 8;
    const int w = t >> 5, lane = t & 31;
    const int ks = w & 3, rh = w >> 2;

    // epilogue mapping: thread owns batch be, j-pair (2*jp, 2*jp+1)
    const int be = t & 63, jp = t >> 6;

    // ---- stage W slice once: 32 rows x 1024 k ----
#pragma unroll
    for (int i = 0; i < 32; i++) {
        int f = t + i * 256;
        int r = f >> 8, kq = (f & 255) << 2;
        int n = (r >> 3) * HID + j0 + (r & 7);   // gate = r>>3, jj = r&7
        float4 v = *(const float4*)(d_whp + (size_t)n * HID + kq);
        *(float4*)(shW + r * PS_WS + kq) = v;
    }

    float creg[2] = {0.0f, 0.0f};

    const int sb = t >> 5, skq = (t & 31) << 2;  // h staging map

    for (int s = 0; s < SEQ; s++) {
        const float* __restrict__ hprev = d_hbuf[s & 1];
        float* __restrict__ hnext = d_hbuf[(s + 1) & 1];

        // ---- prefetch gx gates for this step (latency hidden by GEMM) ----
        float gpre[2][4];
#pragma unroll
        for (int i = 0; i < 2; i++)
#pragma unroll
            for (int gg = 0; gg < 4; gg++)
                gpre[i][gg] = __ldg(&d_gx[((size_t)s * NG + gg * 1024 + j0 + 2 * jp + i) * BB + be]);

        ull acc[16][2];
#pragma unroll
        for (int r = 0; r < 16; r++) { acc[r][0] = 0ULL; acc[r][1] = 0ULL; }

        __syncthreads();   // protect h buffers / red alias from previous step
#pragma unroll
        for (int i = 0; i < 8; i++) {
            int b = sb + i * 8;
            cp16(shH0 + b * PS_HS + skq, hprev + b * HID + 0 + skq);
        }
        cp_commit();

        for (int ch = 0; ch < HID; ch += 128) {
            float* cur = ((ch >> 7) & 1) ? shH1 : shH0;
            float* nxt = ((ch >> 7) & 1) ? shH0 : shH1;
            if (ch + 128 < HID) {
#pragma unroll
                for (int i = 0; i < 8; i++) {
                    int b = sb + i * 8;
                    cp16(nxt + b * PS_HS + skq, hprev + b * HID + ch + 128 + skq);
                }
                cp_commit();
                cp_wait<1>();
            } else {
                cp_wait<0>();
            }
            __syncthreads();

#pragma unroll
            for (int it = 0; it < 8; it++) {
                const int kh = ks * 32 + it * 4;       // within chunk
                ulonglong2 hv0 = *(const ulonglong2*)(cur + lane * PS_HS + kh);
                ulonglong2 hv1 = *(const ulonglong2*)(cur + (lane + 32) * PS_HS + kh);
#pragma unroll
                for (int r = 0; r < 16; r++) {
                    ulonglong2 wv = *(const ulonglong2*)(shW + (rh * 16 + r) * PS_WS + ch + kh);
                    fma2(acc[r][0], wv.x, hv0.x);
                    fma2(acc[r][0], wv.y, hv0.y);
                    fma2(acc[r][1], wv.x, hv1.x);
                    fma2(acc[r][1], wv.y, hv1.y);
                }
            }
            __syncthreads();  // all warps done with 'cur' before refill
        }

        // ---- k-split reduction through smem (red aliases h bufs) ----
#pragma unroll
        for (int r = 0; r < 16; r++) {
            int rr = rh * 16 + r;
            red[(ks * 32 + rr) * PS_RS + lane]      = hsum2(acc[r][0]);
            red[(ks * 32 + rr) * PS_RS + lane + 32] = hsum2(acc[r][1]);
        }
        __syncthreads();

        // ---- pointwise LSTM cell update: thread = (batch be, j-pair jp) ----
        float2 hout;
#pragma unroll
        for (int i = 0; i < 2; i++) {
            int j = 2 * jp + i;
            float g[4];
#pragma unroll
            for (int gg = 0; gg < 4; gg++) {
                int r = gg * 8 + j;
                float v = 0.0f;
#pragma unroll
                for (int kk = 0; kk < 4; kk++)
                    v += red[(kk * 32 + r) * PS_RS + be];
                g[gg] = v + gpre[i][gg];
            }
            float it_ = sigf(g[0]);
            float ft  = sigf(g[1]);
            float gt  = tanhf(g[2]);
            float ot  = sigf(g[3]);
            float c = ft * creg[i] + it_ * gt;
            creg[i] = c;
            ((float*)&hout)[i] = ot * tanhf(c);
        }
        *(float2*)(hnext + be * HID + j0 + 2 * jp) = hout;

        // ---- grid-wide barrier ----
        __threadfence();
        __syncthreads();
        if (t == 0) {
            atomicAdd(&d_bar, 1);
            const int target = 128 * (s + 1);
            while (*(volatile int*)&d_bar < target) { }
        }
        __syncthreads();
    }

    // ---- publish final c ----
    *(float2*)(d_cst + be * HID + j0 + 2 * jp) = make_float2(creg[0], creg[1]);
}

// =====================================================================
// head: out = h @ V_w^T + V_b ; also emit h, c into d_out.
// =====================================================================
__global__ void head_kernel(const float* __restrict__ Vw, const float* __restrict__ Vb,
                            float* __restrict__ out)
{
    const float* hfin = d_hbuf[SEQ & 1];
    const int b = blockIdx.x, t = threadIdx.x;
    float s0 = 0.0f, s1 = 0.0f;
    for (int k = t; k < HID; k += 256) {
        float hv = hfin[b * HID + k];
        s0 += hv * Vw[k];
        s1 += hv * Vw[HID + k];
        out[128 + b * HID + k] = hv;
        out[128 + BB * HID + b * HID + k] = d_cst[b * HID + k];
    }
    __shared__ float r0[256], r1[256];
    r0[t] = s0; r1[t] = s1;
    __syncthreads();
    for (int off = 128; off > 0; off >>= 1) {
        if (t < off) { r0[t] += r0[t + off]; r1[t] += r1[t + off]; }
        __syncthreads();
    }
    if (t == 0) {
        out[b * 2 + 0] = r0[0] + Vb[0];
        out[b * 2 + 1] = r1[0] + Vb[1];
    }
}

// =====================================================================
extern "C" void kernel_launch(void* const* d_in, const int* in_sizes, int n_in,
                              void* d_out, int out_size)
{
    (void)in_sizes; (void)n_in; (void)out_size;
    const int*   x   = (const int*)d_in[0];
    const float* emb = (const float*)d_in[1];

    cudaFuncSetAttribute(gx_kernel,      cudaFuncAttributeMaxDynamicSharedMemorySize, GX_SMEM);
    cudaFuncSetAttribute(persist_kernel, cudaFuncAttributeMaxDynamicSharedMemorySize, PS_SMEM);

    prepack_kernel<<<1024, 256>>>(
        (const float*)d_in[2],  (const float*)d_in[3],  (const float*)d_in[4],
        (const float*)d_in[5],  (const float*)d_in[6],  (const float*)d_in[7],
        (const float*)d_in[8],  (const float*)d_in[9],  (const float*)d_in[10],
        (const float*)d_in[11], (const float*)d_in[12], (const float*)d_in[13]);

    gx_kernel<<<dim3(64, 512), 256, GX_SMEM>>>(x, emb);

    persist_kernel<<<128, 256, PS_SMEM>>>();

    head_kernel<<<BB, 256>>>((const float*)d_in[14], (const float*)d_in[15], (float*)d_out);
}

// round 9
// speedup vs baseline: 1.5451x; 1.4651x over previous
#include <cuda_runtime.h>
#include <cuda_bf16.h>
#include <math.h>

#define SEQ 512
#define BB  64
#define EMB 512
#define HID 1024
#define NG  4096

typedef unsigned long long ull;

// ---------------- device scratch (no runtime allocation) ----------------
__device__ float d_gx[(size_t)SEQ * NG * BB];        // [s][R][b], R = cta*32 + g*8 + jj
__device__ float d_wxp[NG * EMB];                    // packed Wx [n][e] (gate-major n)
__device__ float d_bxp[NG];
__device__ __nv_bfloat16 d_whb[(size_t)2 * NG * HID];// Wh, R_ext = cta*64 + split*32 + local
__device__ __nv_bfloat16 d_hbf[2][BB * HID];         // h split hi/lo, [b][k]
__device__ float d_hfin[BB * HID];                   // final h fp32
__device__ float d_cst[BB * HID];                    // final c fp32
__device__ int   d_bar;

// ---------------- helpers ----------------
__device__ __forceinline__ void fma2(ull& d, ull a, ull b) {
    asm("fma.rn.f32x2 %0, %1, %2, %0;" : "+l"(d) : "l"(a), "l"(b));
}
__device__ __forceinline__ float hsum2(ull v) {
    unsigned lo = (unsigned)(v & 0xffffffffULL);
    unsigned hi = (unsigned)(v >> 32);
    return __uint_as_float(lo) + __uint_as_float(hi);
}
__device__ __forceinline__ float sigf(float x) { return 1.0f / (1.0f + __expf(-x)); }

__device__ __forceinline__ void cp16(void* smem_dst, const void* gsrc) {
    unsigned d = (unsigned)__cvta_generic_to_shared(smem_dst);
    asm volatile("cp.async.cg.shared.global [%0], [%1], 16;" :: "r"(d), "l"(gsrc));
}
__device__ __forceinline__ void cp_commit() { asm volatile("cp.async.commit_group;"); }
template <int N> __device__ __forceinline__ void cp_wait() {
    asm volatile("cp.async.wait_group %0;" :: "n"(N));
}
__device__ __forceinline__ unsigned smem_u32(const void* p) {
    return (unsigned)__cvta_generic_to_shared(p);
}
__device__ __forceinline__ void ldm_x4(unsigned& r0, unsigned& r1, unsigned& r2, unsigned& r3,
                                       unsigned addr) {
    asm volatile("ldmatrix.sync.aligned.m8n8.x4.shared.b16 {%0,%1,%2,%3}, [%4];"
                 : "=r"(r0), "=r"(r1), "=r"(r2), "=r"(r3) : "r"(addr));
}
__device__ __forceinline__ void mma16816(float* d, const unsigned* a, unsigned b0, unsigned b1) {
    asm volatile(
        "mma.sync.aligned.m16n8k16.row.col.f32.bf16.bf16.f32 "
        "{%0,%1,%2,%3}, {%4,%5,%6,%7}, {%8,%9}, {%0,%1,%2,%3};"
        : "+f"(d[0]), "+f"(d[1]), "+f"(d[2]), "+f"(d[3])
        : "r"(a[0]), "r"(a[1]), "r"(a[2]), "r"(a[3]), "r"(b0), "r"(b1));
}

// =====================================================================
// prepack: gate-major Wx/b (fp32); Wh bf16 hi/lo in CTA-slab order:
// R_ext = cta*64 + split*32 + (g*8 + jj), row of W_h{g} = cta*8 + jj.
// =====================================================================
__global__ void prepack_kernel(
    const float* __restrict__ W_ii, const float* __restrict__ b_ii, const float* __restrict__ W_hi,
    const float* __restrict__ W_if, const float* __restrict__ b_if, const float* __restrict__ W_hf,
    const float* __restrict__ W_ig, const float* __restrict__ b_ig, const float* __restrict__ W_hg,
    const float* __restrict__ W_io, const float* __restrict__ b_io, const float* __restrict__ W_ho)
{
    const int stride = gridDim.x * blockDim.x;
    const int tid = blockIdx.x * blockDim.x + threadIdx.x;

    if (tid == 0) d_bar = 0;

    for (int i = tid; i < NG * EMB; i += stride) {
        int n = i / EMB, k = i - n * EMB;
        int g = n >> 10, j = n & 1023;
        const float* w = (g == 0) ? W_ii : (g == 1) ? W_if : (g == 2) ? W_ig : W_io;
        d_wxp[i] = w[j * EMB + k];
    }
    for (int i = tid; i < NG; i += stride) {
        int g = i >> 10, j = i & 1023;
        const float* b = (g == 0) ? b_ii : (g == 1) ? b_if : (g == 2) ? b_ig : b_io;
        d_bxp[i] = b[j];
    }
    for (size_t i = tid; i < (size_t)2 * NG * HID; i += stride) {
        int Re = (int)(i >> 10), k = (int)(i & 1023);
        int cta = Re >> 6, rem = Re & 63;
        int split = rem >> 5, local = rem & 31;
        int g = local >> 3, jj = local & 7;
        int j = cta * 8 + jj;
        const float* w = (g == 0) ? W_hi : (g == 1) ? W_hf : (g == 2) ? W_hg : W_ho;
        float v = w[j * HID + k];
        __nv_bfloat16 hi = __float2bfloat16_rn(v);
        if (split == 0) d_whb[i] = hi;
        else            d_whb[i] = __float2bfloat16_rn(v - __bfloat162float(hi));
    }
    for (int i = tid; i < BB * HID; i += stride) {
        d_hbf[0][i] = __float2bfloat16_rn(0.0f);
        d_hbf[1][i] = __float2bfloat16_rn(0.0f);
    }
}

// =====================================================================
// gx kernel (fp32): stores rows permuted to R order.
// =====================================================================
#define GX_AS 68
#define GX_RS 66
#define GX_BUF (64 * GX_AS)
#define GX_SMEM ((4 * GX_BUF) * 4)

__global__ void __launch_bounds__(256, 2) gx_kernel(const int* __restrict__ x,
                                                    const float* __restrict__ emb)
{
    extern __shared__ float sm[];
    float* shA0 = sm;
    float* shB0 = sm + GX_BUF;
    float* shA1 = sm + 2 * GX_BUF;
    float* shB1 = sm + 3 * GX_BUF;
    float* red  = sm;                  // alias: [2 ks][64 r][66]

    const int t = threadIdx.x;
    const int s = blockIdx.y;
    const int n0 = blockIdx.x * 64;

    __shared__ int tok[64];
    if (t < 64) tok[t] = x[t * SEQ + s];

    const int w = t >> 5, lane = t & 31;
    const int ks = w & 1, rq = w >> 1;

    ull acc[16][2];
#pragma unroll
    for (int r = 0; r < 16; r++) { acc[r][0] = 0ULL; acc[r][1] = 0ULL; }

    const int srow = t >> 4, sseg = (t & 15) * 4;
    __syncthreads();

#pragma unroll
    for (int i = 0; i < 4; i++) {
        int r = srow + i * 16;
        cp16(shA0 + r * GX_AS + sseg, emb + (size_t)tok[r] * EMB + 0 + sseg);
        cp16(shB0 + r * GX_AS + sseg, d_wxp + (size_t)(n0 + r) * EMB + 0 + sseg);
    }
    cp_commit();

    for (int ch = 0; ch < EMB; ch += 64) {
        const bool odd = (ch >> 6) & 1;
        float* curA = odd ? shA1 : shA0;
        float* curB = odd ? shB1 : shB0;
        float* nxtA = odd ? shA0 : shA1;
        float* nxtB = odd ? shB0 : shB1;
        if (ch + 64 < EMB) {
#pragma unroll
            for (int i = 0; i < 4; i++) {
                int r = srow + i * 16;
                cp16(nxtA + r * GX_AS + sseg, emb + (size_t)tok[r] * EMB + ch + 64 + sseg);
                cp16(nxtB + r * GX_AS + sseg, d_wxp + (size_t)(n0 + r) * EMB + ch + 64 + sseg);
            }
            cp_commit();
            cp_wait<1>();
        } else {
            cp_wait<0>();
        }
        __syncthreads();

#pragma unroll
        for (int it = 0; it < 8; it++) {
            const int kl = ks * 32 + it * 4;
            ulonglong2 hv0 = *(const ulonglong2*)(curA + lane * GX_AS + kl);
            ulonglong2 hv1 = *(const ulonglong2*)(curA + (lane + 32) * GX_AS + kl);
#pragma unroll
            for (int r = 0; r < 16; r++) {
                ulonglong2 wv = *(const ulonglong2*)(curB + (rq * 16 + r) * GX_AS + kl);
                fma2(acc[r][0], wv.x, hv0.x);
                fma2(acc[r][0], wv.y, hv0.y);
                fma2(acc[r][1], wv.x, hv1.x);
                fma2(acc[r][1], wv.y, hv1.y);
            }
        }
        __syncthreads();
    }

#pragma unroll
    for (int r = 0; r < 16; r++) {
        int rr = rq * 16 + r;
        red[(ks * 64 + rr) * GX_RS + lane]      = hsum2(acc[r][0]);
        red[(ks * 64 + rr) * GX_RS + lane + 32] = hsum2(acc[r][1]);
    }
    __syncthreads();
#pragma unroll
    for (int i = 0; i < 16; i++) {
        int cell = t + i * 256;
        int r = cell >> 6, b = cell & 63;
        float v = red[r * GX_RS + b] + red[(64 + r) * GX_RS + b] + d_bxp[n0 + r];
        int n = n0 + r;
        int g = n >> 10, j = n & 1023;
        int R = (j >> 3) * 32 + g * 8 + (j & 7);
        d_gx[((size_t)s * NG + R) * BB + b] = v;
    }
}

// =====================================================================
// persistent mma.sync step kernel. 128 CTAs x 256 threads, 1 CTA/SM.
// CTA owns 32 rows (4 gates x 8 j, j0 = cta*8). W hi+lo (64 ext rows x
// 1024 k bf16, pitch 2064B -> ldmatrix conflict-free) staged to SMEM once.
// Per step: D[32,64] = 3-term bf16 split GEMM, K chunks of 128 double-
// buffered via cp.async; each chunk (hhi+hlo) reused by all 3 segments.
// Warp tile 16m x 16n (wm = w>>2, wn = w&3); per k16: 2 ldmatrix.x4 +
// 2 mma.m16n8k16. Epilogue via smem gate buffer + gx prefetch. c in regs.
// =====================================================================
#define W_PITCH 2064                       // bytes; 516 words, mod32 = 4
#define H_PITCH 272                        // bytes; 68 words, mod32 = 4
#define HBUF (64 * H_PITCH)                // 17408 B per split
#define OFF_W   0                          // 64 * 2064 = 132096
#define OFF_H   132096                     // 2 bufs x 2 splits x 17408 = 69632
#define OFF_SG  201728                     // 32*68*4 = 8704
#define OFF_SGX 210432                     // 8704
#define TC_SMEM 219136

__global__ void __launch_bounds__(256, 1) persist_mma_kernel()
{
    extern __shared__ char smc[];
    float* sg  = (float*)(smc + OFF_SG);
    float* sgx = (float*)(smc + OFF_SGX);

    const int t = threadIdx.x, w = t >> 5, lane = t & 31;
    const int cta = blockIdx.x;
    const int wm = w >> 2, wn = w & 3;
    const unsigned smb = smem_u32(smc);

    // ---- stage W slab once: 64 ext rows x 2048 B ----
    const char* wsrc = (const char*)(d_whb + (size_t)cta * 64 * HID);
#pragma unroll
    for (int i = 0; i < 32; i++) {
        int u = t + i * 256;
        int r = u >> 7, q = u & 127;
        cp16(smc + OFF_W + r * W_PITCH + q * 16, wsrc + r * 2048 + q * 16);
    }
    cp_commit(); cp_wait<0>();
    __syncthreads();

    // ldmatrix lane mapping: row = lane&15, k-half = (lane>=16) ? +16B : 0
    const int lrow = lane & 15;
    const int kh2 = (lane >> 4) * 16;      // byte offset of k-half (8 bf16)

    // pointwise mapping
    const int be = t & 63, jp = t >> 6;    // jj = 2*jp, 2*jp+1
    float creg[2] = {0.0f, 0.0f};

    for (int s = 0; s < SEQ; s++) {
        // ---- prologue: gx prefetch + h chunk 0 (one group) ----
#pragma unroll
        for (int i = 0; i < 2; i++) {
            int u = t + i * 256;
            int r = u >> 4, bq = (u & 15) * 4;
            cp16((char*)sgx + (r * 68 + bq) * 4,
                 d_gx + ((size_t)s * NG + cta * 32 + r) * BB + bq);
        }
#pragma unroll
        for (int i = 0; i < 8; i++) {
            int u = t + i * 256;
            int split = u >> 10, r = (u >> 4) & 63, q = u & 15;
            cp16(smc + OFF_H + split * HBUF + r * H_PITCH + q * 16,
                 (const char*)d_hbf[split] + r * 2048 + 0 + q * 16);
        }
        cp_commit();

        float d[2][4];
#pragma unroll
        for (int nt = 0; nt < 2; nt++)
#pragma unroll
            for (int q = 0; q < 4; q++) d[nt][q] = 0.0f;

        for (int kb = 0; kb < 8; kb++) {
            __syncthreads();   // all warps done computing on buf (kb+1)&1
            if (kb < 7) {
                char* nxt = smc + OFF_H + ((kb + 1) & 1) * 2 * HBUF;
#pragma unroll
                for (int i = 0; i < 8; i++) {
                    int u = t + i * 256;
                    int split = u >> 10, r = (u >> 4) & 63, q = u & 15;
                    cp16(nxt + split * HBUF + r * H_PITCH + q * 16,
                         (const char*)d_hbf[split] + r * 2048 + (kb + 1) * 256 + q * 16);
                }
                cp_commit();
                cp_wait<1>();
            } else {
                cp_wait<0>();
            }
            __syncthreads();   // chunk kb visible

            const unsigned hbase = smb + OFF_H + (kb & 1) * 2 * HBUF;
#pragma unroll
            for (int seg = 0; seg < 3; seg++) {
                const unsigned abase = smb + OFF_W + (seg == 1 ? 32 * W_PITCH : 0)
                                     + (wm * 16 + lrow) * W_PITCH
                                     + kb * 256;                       // K-chunk offset (FIX)
                const unsigned bbase = hbase + (seg == 2 ? HBUF : 0)
                                     + (wn * 16 + lrow) * H_PITCH;
#pragma unroll
                for (int k16 = 0; k16 < 8; k16++) {
                    const int kB = k16 * 32 + kh2;   // bytes within 128-k chunk rows
                    unsigned a[4], b0, b1, b2, b3;
                    ldm_x4(a[0], a[1], a[2], a[3], abase + kB);
                    ldm_x4(b0, b1, b2, b3, bbase + kB);
                    mma16816(d[0], a, b0, b2);
                    mma16816(d[1], a, b1, b3);
                }
            }
        }
        __syncthreads();

        // ---- write D tiles into sg[row][b] ----
#pragma unroll
        for (int nt = 0; nt < 2; nt++) {
            int col = wn * 16 + nt * 8 + (lane & 3) * 2;
            int row = wm * 16 + (lane >> 2);
            sg[row * 68 + col]           = d[nt][0];
            sg[row * 68 + col + 1]       = d[nt][1];
            sg[(row + 8) * 68 + col]     = d[nt][2];
            sg[(row + 8) * 68 + col + 1] = d[nt][3];
        }
        __syncthreads();

        // ---- pointwise: thread = (be, jj = 2jp, 2jp+1) ----
        unsigned short hhi[2], hlo[2];
        float hf[2];
#pragma unroll
        for (int i = 0; i < 2; i++) {
            int jj = 2 * jp + i;
            float g[4];
#pragma unroll
            for (int gg = 0; gg < 4; gg++) {
                int r = gg * 8 + jj;
                g[gg] = sg[r * 68 + be] + sgx[r * 68 + be];
            }
            float it_ = sigf(g[0]);
            float ft  = sigf(g[1]);
            float gt  = tanhf(g[2]);
            float ot  = sigf(g[3]);
            float c = ft * creg[i] + it_ * gt;
            creg[i] = c;
            float h = ot * tanhf(c);
            hf[i] = h;
            __nv_bfloat16 hh = __float2bfloat16_rn(h);
            __nv_bfloat16 hl = __float2bfloat16_rn(h - __bfloat162float(hh));
            hhi[i] = *(unsigned short*)&hh;
            hlo[i] = *(unsigned short*)&hl;
        }
        const int jglob = cta * 8 + 2 * jp;
        *(unsigned*)(&d_hbf[0][be * HID + jglob]) = *(unsigned*)hhi;
        *(unsigned*)(&d_hbf[1][be * HID + jglob]) = *(unsigned*)hlo;
        if (s == SEQ - 1)
            *(float2*)(&d_hfin[be * HID + jglob]) = make_float2(hf[0], hf[1]);

        // ---- grid-wide barrier (128 CTAs) ----
        __threadfence();
        __syncthreads();
        if (t == 0) {
            atomicAdd(&d_bar, 1);
            const int target = 128 * (s + 1);
            while (*(volatile int*)&d_bar < target) { }
        }
        __syncthreads();
    }

    const int jglob = cta * 8 + 2 * jp;
    *(float2*)(&d_cst[be * HID + jglob]) = make_float2(creg[0], creg[1]);
}

// =====================================================================
// head: out = h @ V_w^T + V_b ; emit h, c.
// =====================================================================
__global__ void head_kernel(const float* __restrict__ Vw, const float* __restrict__ Vb,
                            float* __restrict__ out)
{
    const int b = blockIdx.x, t = threadIdx.x;
    float s0 = 0.0f, s1 = 0.0f;
    for (int k = t; k < HID; k += 256) {
        float hv = d_hfin[b * HID + k];
        s0 += hv * Vw[k];
        s1 += hv * Vw[HID + k];
        out[128 + b * HID + k] = hv;
        out[128 + BB * HID + b * HID + k] = d_cst[b * HID + k];
    }
    __shared__ float r0[256], r1[256];
    r0[t] = s0; r1[t] = s1;
    __syncthreads();
    for (int off = 128; off > 0; off >>= 1) {
        if (t < off) { r0[t] += r0[t + off]; r1[t] += r1[t + off]; }
        __syncthreads();
    }
    if (t == 0) {
        out[b * 2 + 0] = r0[0] + Vb[0];
        out[b * 2 + 1] = r1[0] + Vb[1];
    }
}

// =====================================================================
extern "C" void kernel_launch(void* const* d_in, const int* in_sizes, int n_in,
                              void* d_out, int out_size)
{
    (void)in_sizes; (void)n_in; (void)out_size;
    const int*   x   = (const int*)d_in[0];
    const float* emb = (const float*)d_in[1];

    cudaFuncSetAttribute(gx_kernel,          cudaFuncAttributeMaxDynamicSharedMemorySize, GX_SMEM);
    cudaFuncSetAttribute(persist_mma_kernel, cudaFuncAttributeMaxDynamicSharedMemorySize, TC_SMEM);

    prepack_kernel<<<1024, 256>>>(
        (const float*)d_in[2],  (const float*)d_in[3],  (const float*)d_in[4],
        (const float*)d_in[5],  (const float*)d_in[6],  (const float*)d_in[7],
        (const float*)d_in[8],  (const float*)d_in[9],  (const float*)d_in[10],
        (const float*)d_in[11], (const float*)d_in[12], (const float*)d_in[13]);

    gx_kernel<<<dim3(64, 512), 256, GX_SMEM>>>(x, emb);

    persist_mma_kernel<<<128, 256, TC_SMEM>>>();

    head_kernel<<<BB, 256>>>((const float*)d_in[14], (const float*)d_in[15], (float*)d_out);
}

// round 10
// speedup vs baseline: 1.9788x; 1.2807x over previous
#include <cuda_runtime.h>
#include <cuda_bf16.h>
#include <math.h>

#define SEQ 512
#define BB  64
#define EMB 512
#define HID 1024
#define NG  4096
#define NM  32768   // N dim of gx GEMM = SEQ*BB

typedef unsigned long long ull;

// ---------------- device scratch (no runtime allocation) ----------------
__device__ float d_gx[(size_t)SEQ * NG * BB];                  // [s][R][b]
__device__ __align__(16) __nv_bfloat16 d_wxb[(size_t)2 * NG * EMB];   // Wx hi/lo, R-order
__device__ float d_bxr[NG];                                    // bias, R-order
__device__ __align__(16) __nv_bfloat16 d_whb[(size_t)2 * NG * HID];   // Wh hi/lo, cta-slab order
__device__ __align__(16) __nv_bfloat16 d_ebf[(size_t)2 * NM * EMB];   // gathered emb hi/lo [m][k]
__device__ __align__(16) __nv_bfloat16 d_hbf[2][BB * HID];     // h split hi/lo [b][k]
__device__ float d_hfin[BB * HID];
__device__ float d_cst[BB * HID];
__device__ int   d_bar;

// ---------------- helpers ----------------
__device__ __forceinline__ float sigf(float x) { return 1.0f / (1.0f + __expf(-x)); }

__device__ __forceinline__ void cp16(void* smem_dst, const void* gsrc) {
    unsigned d = (unsigned)__cvta_generic_to_shared(smem_dst);
    asm volatile("cp.async.cg.shared.global [%0], [%1], 16;" :: "r"(d), "l"(gsrc));
}
__device__ __forceinline__ void cp_commit() { asm volatile("cp.async.commit_group;"); }
template <int N> __device__ __forceinline__ void cp_wait() {
    asm volatile("cp.async.wait_group %0;" :: "n"(N));
}
__device__ __forceinline__ unsigned smem_u32(const void* p) {
    return (unsigned)__cvta_generic_to_shared(p);
}
__device__ __forceinline__ void ldm_x4(unsigned& r0, unsigned& r1, unsigned& r2, unsigned& r3,
                                       unsigned addr) {
    asm volatile("ldmatrix.sync.aligned.m8n8.x4.shared.b16 {%0,%1,%2,%3}, [%4];"
                 : "=r"(r0), "=r"(r1), "=r"(r2), "=r"(r3) : "r"(addr));
}
__device__ __forceinline__ void mma16816(float* d, const unsigned* a, unsigned b0, unsigned b1) {
    asm volatile(
        "mma.sync.aligned.m16n8k16.row.col.f32.bf16.bf16.f32 "
        "{%0,%1,%2,%3}, {%4,%5,%6,%7}, {%8,%9}, {%0,%1,%2,%3};"
        : "+f"(d[0]), "+f"(d[1]), "+f"(d[2]), "+f"(d[3])
        : "r"(a[0]), "r"(a[1]), "r"(a[2]), "r"(a[3]), "r"(b0), "r"(b1));
}
__device__ __forceinline__ ull pack4bf(float a, float b, float c, float d,
                                       float& la, float& lb, float& lc, float& ld) {
    __nv_bfloat16 h0 = __float2bfloat16_rn(a), h1 = __float2bfloat16_rn(b);
    __nv_bfloat16 h2 = __float2bfloat16_rn(c), h3 = __float2bfloat16_rn(d);
    la = a - __bfloat162float(h0); lb = b - __bfloat162float(h1);
    lc = c - __bfloat162float(h2); ld = d - __bfloat162float(h3);
    ull r = (ull)*(unsigned short*)&h0 | ((ull)*(unsigned short*)&h1 << 16)
          | ((ull)*(unsigned short*)&h2 << 32) | ((ull)*(unsigned short*)&h3 << 48);
    return r;
}

// =====================================================================
// prepack: R-ordered Wx/bias (R = (j>>3)*32 + g*8 + (j&7)); Wh hi/lo
// cta-slab order (R_ext = cta*64 + split*32 + g*8 + jj); zero h splits.
// =====================================================================
__global__ void prepack_kernel(
    const float* __restrict__ W_ii, const float* __restrict__ b_ii, const float* __restrict__ W_hi,
    const float* __restrict__ W_if, const float* __restrict__ b_if, const float* __restrict__ W_hf,
    const float* __restrict__ W_ig, const float* __restrict__ b_ig, const float* __restrict__ W_hg,
    const float* __restrict__ W_io, const float* __restrict__ b_io, const float* __restrict__ W_ho)
{
    const size_t stride = (size_t)gridDim.x * blockDim.x;
    const size_t tid = (size_t)blockIdx.x * blockDim.x + threadIdx.x;

    if (tid == 0) d_bar = 0;

    // Wx hi/lo in R order
    for (size_t i = tid; i < (size_t)NG * EMB; i += stride) {
        int R = (int)(i >> 9), k = (int)(i & 511);
        int cta = R >> 5, g = (R >> 3) & 3, jj = R & 7;
        int j = cta * 8 + jj;
        const float* w = (g == 0) ? W_ii : (g == 1) ? W_if : (g == 2) ? W_ig : W_io;
        float v = w[j * EMB + k];
        __nv_bfloat16 hi = __float2bfloat16_rn(v);
        d_wxb[i] = hi;
        d_wxb[(size_t)NG * EMB + i] = __float2bfloat16_rn(v - __bfloat162float(hi));
    }
    for (size_t i = tid; i < NG; i += stride) {
        int R = (int)i;
        int cta = R >> 5, g = (R >> 3) & 3, jj = R & 7;
        int j = cta * 8 + jj;
        const float* b = (g == 0) ? b_ii : (g == 1) ? b_if : (g == 2) ? b_ig : b_io;
        d_bxr[R] = b[j];
    }
    // Wh hi/lo in persist slab order
    for (size_t i = tid; i < (size_t)2 * NG * HID; i += stride) {
        int Re = (int)(i >> 10), k = (int)(i & 1023);
        int cta = Re >> 6, rem = Re & 63;
        int split = rem >> 5, local = rem & 31;
        int g = local >> 3, jj = local & 7;
        int j = cta * 8 + jj;
        const float* w = (g == 0) ? W_hi : (g == 1) ? W_hf : (g == 2) ? W_hg : W_ho;
        float v = w[j * HID + k];
        __nv_bfloat16 hi = __float2bfloat16_rn(v);
        if (split == 0) d_whb[i] = hi;
        else            d_whb[i] = __float2bfloat16_rn(v - __bfloat162float(hi));
    }
    for (size_t i = tid; i < BB * HID; i += stride) {
        d_hbf[0][i] = __float2bfloat16_rn(0.0f);
        d_hbf[1][i] = __float2bfloat16_rn(0.0f);
    }
}

// =====================================================================
// gather: e rows m = s*64+b -> bf16 hi/lo split [m][k].
// =====================================================================
__global__ void gather_kernel(const int* __restrict__ x, const float* __restrict__ emb)
{
    ull* ehi = (ull*)d_ebf;
    ull* elo = (ull*)(d_ebf + (size_t)NM * EMB);
    const size_t stride = (size_t)gridDim.x * blockDim.x;
    for (size_t idx = (size_t)blockIdx.x * blockDim.x + threadIdx.x;
         idx < (size_t)NM * 128; idx += stride) {
        int m = (int)(idx >> 7), q = (int)(idx & 127);
        int s = m >> 6, b = m & 63;
        int tok = __ldg(&x[b * SEQ + s]);
        float4 v = *(const float4*)(emb + (size_t)tok * EMB + q * 4);
        float la, lb, lc, ld;
        ull hv = pack4bf(v.x, v.y, v.z, v.w, la, lb, lc, ld);
        float dum0, dum1, dum2, dum3;
        ull lv = pack4bf(la, lb, lc, ld, dum0, dum1, dum2, dum3);
        ehi[(size_t)m * 128 + q] = hv;
        elo[(size_t)m * 128 + q] = lv;
    }
}

// =====================================================================
// gx2: HMMA GEMM  d_gx[s][R][b] = Wx(R-order) x e + bias.
// M=4096(R), N=32768(m = s*64+b), K=512, bf16 3-term split.
// Grid (32 mtiles, 256 ntiles); CTA tile 128R x 128m; 8 warps = 4m x 2n;
// warp tile 32R x 64m. 64-k chunks, double-buffered cp.async.
// Pitch 144B (== 4 words mod 32 per row step -> ldmatrix conflict-free).
// =====================================================================
#define G2_PITCH 144
#define G2_SPL   18432            // 128 * 144
#define G2_BUFSZ 36864            // 2 splits
#define G2_OFF_B 73728            // A total (2 bufs)
#define G2_SMEM  147456

__global__ void __launch_bounds__(256, 1) gx2_kernel()
{
    extern __shared__ char smc[];
    const unsigned smb = smem_u32(smc);
    const int t = threadIdx.x, w = t >> 5, lane = t & 31;
    const int mty = blockIdx.x;            // 0..31
    const int ntx = blockIdx.y;            // 0..255
    const int wm = w >> 1, wn = w & 1;     // 4m x 2n warp grid
    const int lrow = lane & 15;
    const int kh2 = (lane >> 4) * 16;

    const __nv_bfloat16* wsrc = d_wxb;
    const __nv_bfloat16* esrc = d_ebf;

    float d[2][4][2][4];
#pragma unroll
    for (int mt = 0; mt < 2; mt++)
#pragma unroll
        for (int bt = 0; bt < 4; bt++)
#pragma unroll
            for (int hf = 0; hf < 2; hf++)
#pragma unroll
                for (int q = 0; q < 4; q++) d[mt][bt][hf][q] = 0.0f;

    // staging decode: u = t + i*256 (i<8): split = u>>10, r = (u>>3)&127, q = u&7
    const int ssplit = (t + 0) >> 10;   // recomputed per i below (t<256 so depends on i)

    auto stage = [&](int cb) {
        const int buf = cb & 1;
        char* abase = smc + buf * G2_BUFSZ;
        char* bbase = smc + G2_OFF_B + buf * G2_BUFSZ;
#pragma unroll
        for (int i = 0; i < 8; i++) {
            int u = t + i * 256;
            int split = u >> 10, r = (u >> 3) & 127, q = u & 7;
            cp16(abase + split * G2_SPL + r * G2_PITCH + q * 16,
                 wsrc + (size_t)split * NG * EMB + (size_t)(mty * 128 + r) * EMB + cb * 64 + q * 8);
        }
#pragma unroll
        for (int i = 0; i < 8; i++) {
            int u = t + i * 256;
            int split = u >> 10, r = (u >> 3) & 127, q = u & 7;
            cp16(bbase + split * G2_SPL + r * G2_PITCH + q * 16,
                 esrc + (size_t)split * NM * EMB + (size_t)(ntx * 128 + r) * EMB + cb * 64 + q * 8);
        }
        cp_commit();
    };
    (void)ssplit;

    stage(0);

    for (int cb = 0; cb < 8; cb++) {
        if (cb < 7) { stage(cb + 1); cp_wait<1>(); }
        else        { cp_wait<0>(); }
        __syncthreads();

        const unsigned abase = smb + (cb & 1) * G2_BUFSZ;
        const unsigned bbase = smb + G2_OFF_B + (cb & 1) * G2_BUFSZ;
#pragma unroll
        for (int k16 = 0; k16 < 4; k16++) {
            const int kB = k16 * 32 + kh2;
            unsigned Ah[2][4], Al[2][4];
#pragma unroll
            for (int mt = 0; mt < 2; mt++) {
                unsigned ar = abase + (wm * 32 + mt * 16 + lrow) * G2_PITCH + kB;
                ldm_x4(Ah[mt][0], Ah[mt][1], Ah[mt][2], Ah[mt][3], ar);
                ldm_x4(Al[mt][0], Al[mt][1], Al[mt][2], Al[mt][3], ar + G2_SPL);
            }
#pragma unroll
            for (int bt = 0; bt < 4; bt++) {
                unsigned br = bbase + (wn * 64 + bt * 16 + lrow) * G2_PITCH + kB;
                unsigned bh0, bh1, bh2, bh3, bl0, bl1, bl2, bl3;
                ldm_x4(bh0, bh1, bh2, bh3, br);
                ldm_x4(bl0, bl1, bl2, bl3, br + G2_SPL);
#pragma unroll
                for (int mt = 0; mt < 2; mt++) {
                    mma16816(d[mt][bt][0], Ah[mt], bh0, bh2);
                    mma16816(d[mt][bt][1], Ah[mt], bh1, bh3);
                    mma16816(d[mt][bt][0], Al[mt], bh0, bh2);
                    mma16816(d[mt][bt][1], Al[mt], bh1, bh3);
                    mma16816(d[mt][bt][0], Ah[mt], bl0, bl2);
                    mma16816(d[mt][bt][1], Ah[mt], bl1, bl3);
                }
            }
        }
        __syncthreads();
    }

    // ---- epilogue: write d_gx[s][R][b] with bias, float2 stores ----
#pragma unroll
    for (int mt = 0; mt < 2; mt++) {
        int Rg0 = mty * 128 + wm * 32 + mt * 16 + (lane >> 2);
        int Rg1 = Rg0 + 8;
        float bi0 = __ldg(&d_bxr[Rg0]);
        float bi1 = __ldg(&d_bxr[Rg1]);
#pragma unroll
        for (int bt = 0; bt < 4; bt++)
#pragma unroll
            for (int hf = 0; hf < 2; hf++) {
                int col = wn * 64 + bt * 16 + hf * 8 + 2 * (lane & 3);
                int m = ntx * 128 + col;
                int s = m >> 6, b = m & 63;
                float* q = d[mt][bt][hf];
                *(float2*)(&d_gx[((size_t)s * NG + Rg0) * BB + b]) =
                    make_float2(q[0] + bi0, q[1] + bi0);
                *(float2*)(&d_gx[((size_t)s * NG + Rg1) * BB + b]) =
                    make_float2(q[2] + bi1, q[3] + bi1);
            }
    }
}

// =====================================================================
// persistent mma.sync step kernel (as round 9, + fragment reuse).
// =====================================================================
#define W_PITCH 2064
#define H_PITCH 272
#define HBUF (64 * H_PITCH)
#define OFF_W   0
#define OFF_H   132096
#define OFF_SG  201728
#define OFF_SGX 210432
#define TC_SMEM 219136

__global__ void __launch_bounds__(256, 1) persist_mma_kernel()
{
    extern __shared__ char smc[];
    float* sg  = (float*)(smc + OFF_SG);
    float* sgx = (float*)(smc + OFF_SGX);

    const int t = threadIdx.x, w = t >> 5, lane = t & 31;
    const int cta = blockIdx.x;
    const int wm = w >> 2, wn = w & 3;
    const unsigned smb = smem_u32(smc);

    // ---- stage W slab once: 64 ext rows x 2048 B ----
    const char* wsrc = (const char*)(d_whb + (size_t)cta * 64 * HID);
#pragma unroll
    for (int i = 0; i < 32; i++) {
        int u = t + i * 256;
        int r = u >> 7, q = u & 127;
        cp16(smc + OFF_W + r * W_PITCH + q * 16, wsrc + r * 2048 + q * 16);
    }
    cp_commit(); cp_wait<0>();
    __syncthreads();

    const int lrow = lane & 15;
    const int kh2 = (lane >> 4) * 16;

    const int be = t & 63, jp = t >> 6;
    float creg[2] = {0.0f, 0.0f};

    for (int s = 0; s < SEQ; s++) {
        // prologue: gx prefetch + h chunk 0
#pragma unroll
        for (int i = 0; i < 2; i++) {
            int u = t + i * 256;
            int r = u >> 4, bq = (u & 15) * 4;
            cp16((char*)sgx + (r * 68 + bq) * 4,
                 d_gx + ((size_t)s * NG + cta * 32 + r) * BB + bq);
        }
#pragma unroll
        for (int i = 0; i < 8; i++) {
            int u = t + i * 256;
            int split = u >> 10, r = (u >> 4) & 63, q = u & 15;
            cp16(smc + OFF_H + split * HBUF + r * H_PITCH + q * 16,
                 (const char*)d_hbf[split] + r * 2048 + 0 + q * 16);
        }
        cp_commit();

        float d[2][4];
#pragma unroll
        for (int nt = 0; nt < 2; nt++)
#pragma unroll
            for (int q = 0; q < 4; q++) d[nt][q] = 0.0f;

        for (int kb = 0; kb < 8; kb++) {
            __syncthreads();
            if (kb < 7) {
                char* nxt = smc + OFF_H + ((kb + 1) & 1) * 2 * HBUF;
#pragma unroll
                for (int i = 0; i < 8; i++) {
                    int u = t + i * 256;
                    int split = u >> 10, r = (u >> 4) & 63, q = u & 15;
                    cp16(nxt + split * HBUF + r * H_PITCH + q * 16,
                         (const char*)d_hbf[split] + r * 2048 + (kb + 1) * 256 + q * 16);
                }
                cp_commit();
                cp_wait<1>();
            } else {
                cp_wait<0>();
            }
            __syncthreads();

            const unsigned aw = smb + OFF_W + (wm * 16 + lrow) * W_PITCH + kb * 256;
            const unsigned hb = smb + OFF_H + (kb & 1) * 2 * HBUF + (wn * 16 + lrow) * H_PITCH;
#pragma unroll
            for (int k16 = 0; k16 < 8; k16++) {
                const int kB = k16 * 32 + kh2;
                unsigned ah[4], al[4];
                unsigned bh0, bh1, bh2, bh3, bl0, bl1, bl2, bl3;
                ldm_x4(ah[0], ah[1], ah[2], ah[3], aw + kB);
                ldm_x4(al[0], al[1], al[2], al[3], aw + 32 * W_PITCH + kB);
                ldm_x4(bh0, bh1, bh2, bh3, hb + kB);
                ldm_x4(bl0, bl1, bl2, bl3, hb + HBUF + kB);
                mma16816(d[0], ah, bh0, bh2);
                mma16816(d[1], ah, bh1, bh3);
                mma16816(d[0], al, bh0, bh2);
                mma16816(d[1], al, bh1, bh3);
                mma16816(d[0], ah, bl0, bl2);
                mma16816(d[1], ah, bl1, bl3);
            }
        }
        __syncthreads();

#pragma unroll
        for (int nt = 0; nt < 2; nt++) {
            int col = wn * 16 + nt * 8 + (lane & 3) * 2;
            int row = wm * 16 + (lane >> 2);
            sg[row * 68 + col]           = d[nt][0];
            sg[row * 68 + col + 1]       = d[nt][1];
            sg[(row + 8) * 68 + col]     = d[nt][2];
            sg[(row + 8) * 68 + col + 1] = d[nt][3];
        }
        __syncthreads();

        unsigned short hhi[2], hlo[2];
        float hf[2];
#pragma unroll
        for (int i = 0; i < 2; i++) {
            int jj = 2 * jp + i;
            float g[4];
#pragma unroll
            for (int gg = 0; gg < 4; gg++) {
                int r = gg * 8 + jj;
                g[gg] = sg[r * 68 + be] + sgx[r * 68 + be];
            }
            float it_ = sigf(g[0]);
            float ft  = sigf(g[1]);
            float gt  = tanhf(g[2]);
            float ot  = sigf(g[3]);
            float c = ft * creg[i] + it_ * gt;
            creg[i] = c;
            float h = ot * tanhf(c);
            hf[i] = h;
            __nv_bfloat16 hh = __float2bfloat16_rn(h);
            __nv_bfloat16 hl = __float2bfloat16_rn(h - __bfloat162float(hh));
            hhi[i] = *(unsigned short*)&hh;
            hlo[i] = *(unsigned short*)&hl;
        }
        const int jglob = cta * 8 + 2 * jp;
        *(unsigned*)(&d_hbf[0][be * HID + jglob]) = *(unsigned*)hhi;
        *(unsigned*)(&d_hbf[1][be * HID + jglob]) = *(unsigned*)hlo;
        if (s == SEQ - 1)
            *(float2*)(&d_hfin[be * HID + jglob]) = make_float2(hf[0], hf[1]);

        __threadfence();
        __syncthreads();
        if (t == 0) {
            atomicAdd(&d_bar, 1);
            const int target = 128 * (s + 1);
            while (*(volatile int*)&d_bar < target) { }
        }
        __syncthreads();
    }

    const int jglob = cta * 8 + 2 * jp;
    *(float2*)(&d_cst[be * HID + jglob]) = make_float2(creg[0], creg[1]);
}

// =====================================================================
// head
// =====================================================================
__global__ void head_kernel(const float* __restrict__ Vw, const float* __restrict__ Vb,
                            float* __restrict__ out)
{
    const int b = blockIdx.x, t = threadIdx.x;
    float s0 = 0.0f, s1 = 0.0f;
    for (int k = t; k < HID; k += 256) {
        float hv = d_hfin[b * HID + k];
        s0 += hv * Vw[k];
        s1 += hv * Vw[HID + k];
        out[128 + b * HID + k] = hv;
        out[128 + BB * HID + b * HID + k] = d_cst[b * HID + k];
    }
    __shared__ float r0[256], r1[256];
    r0[t] = s0; r1[t] = s1;
    __syncthreads();
    for (int off = 128; off > 0; off >>= 1) {
        if (t < off) { r0[t] += r0[t + off]; r1[t] += r1[t + off]; }
        __syncthreads();
    }
    if (t == 0) {
        out[b * 2 + 0] = r0[0] + Vb[0];
        out[b * 2 + 1] = r1[0] + Vb[1];
    }
}

// =====================================================================
extern "C" void kernel_launch(void* const* d_in, const int* in_sizes, int n_in,
                              void* d_out, int out_size)
{
    (void)in_sizes; (void)n_in; (void)out_size;
    const int*   x   = (const int*)d_in[0];
    const float* emb = (const float*)d_in[1];

    cudaFuncSetAttribute(gx2_kernel,         cudaFuncAttributeMaxDynamicSharedMemorySize, G2_SMEM);
    cudaFuncSetAttribute(persist_mma_kernel, cudaFuncAttributeMaxDynamicSharedMemorySize, TC_SMEM);

    prepack_kernel<<<1024, 256>>>(
        (const float*)d_in[2],  (const float*)d_in[3],  (const float*)d_in[4],
        (const float*)d_in[5],  (const float*)d_in[6],  (const float*)d_in[7],
        (const float*)d_in[8],  (const float*)d_in[9],  (const float*)d_in[10],
        (const float*)d_in[11], (const float*)d_in[12], (const float*)d_in[13]);

    gather_kernel<<<2048, 256>>>(x, emb);

    gx2_kernel<<<dim3(32, 256), 256, G2_SMEM>>>();

    persist_mma_kernel<<<128, 256, TC_SMEM>>>();

    head_kernel<<<BB, 256>>>((const float*)d_in[14], (const float*)d_in[15], (float*)d_out);
}